// round 6
// baseline (speedup 1.0000x reference)
#include <cuda_runtime.h>

#define BATCH 32
#define NPTS 512
#define DIM 1024
#define KCL 64
#define NROWS (BATCH*NPTS)      /* 16384 */
#define OUTF 1024
#define IN2 (2*DIM*KCL)         /* 131072 */
#define HALF1 (DIM*KCL)         /* 65536 */

// ---------------- scratch (device globals: no allocations allowed) ----------
__device__ float g_act[NROWS*KCL];          // 4 MB
__device__ float g_colsum[KCL];
__device__ float g_colsumsq[KCL];
__device__ float g_asum[BATCH*KCL];
__device__ float g_fv1[BATCH*DIM*KCL];      // 8 MB
__device__ float g_fv2[BATCH*DIM*KCL];      // 8 MB
__device__ float g_colnorm[BATCH*KCL];
__device__ float g_norm2[BATCH];
__device__ float g_scale1[BATCH*KCL];
__device__ float g_scale2[BATCH];
__device__ float g_fvout[BATCH*OUTF];
__device__ float g_gates[BATCH*OUTF];

typedef unsigned long long ull;

// ---------------- f32x2 helpers (FFMA2: 2 FMAs / instr on sm_103a) ----------
__device__ __forceinline__ ull pack2(float lo, float hi){
  ull r;
  asm("mov.b64 %0, {%1, %2};" : "=l"(r)
      : "r"(__float_as_uint(lo)), "r"(__float_as_uint(hi)));
  return r;
}
__device__ __forceinline__ void ffma2(ull &d, ull a, ull b){
  asm("fma.rn.f32x2 %0, %1, %2, %3;" : "=l"(d) : "l"(a), "l"(b), "l"(d));
}
__device__ __forceinline__ ull mul2(ull a, ull b){
  ull r; asm("mul.rn.f32x2 %0, %1, %2;" : "=l"(r) : "l"(a), "l"(b)); return r;
}
__device__ __forceinline__ float lo32(ull v){ return __uint_as_float((unsigned)(v & 0xffffffffull)); }
__device__ __forceinline__ float hi32(ull v){ return __uint_as_float((unsigned)(v >> 32)); }

// ---------------- K0: zero the atomic accumulators ---------------------------
__global__ void zero_kernel(){
  int i = blockIdx.x*blockDim.x + threadIdx.x;
  if (i < BATCH*OUTF){ g_fvout[i] = 0.f; g_gates[i] = 0.f; }
  if (i < BATCH*KCL){ g_colnorm[i] = 0.f; g_asum[i] = 0.f; }
  if (i < KCL){ g_colsum[i] = 0.f; g_colsumsq[i] = 0.f; }
  if (i < BATCH) g_norm2[i] = 0.f;
}

// ---------------- K1: act_raw = X @ Wc  (+ column sum / sumsq for BN1) ------
__global__ __launch_bounds__(256) void gemm_act_kernel(
    const float* __restrict__ x, const float* __restrict__ wc){
  __shared__ float As[64][33];
  __shared__ float Bs[32][64];
  __shared__ float sSum[KCL], sSq[KCL];
  int tid = threadIdx.x;
  int row0 = blockIdx.x * 64;
  int tx = tid & 15, ty = tid >> 4;
  ull acc[4][2];
  #pragma unroll
  for (int i=0;i<4;i++){ acc[i][0]=0ull; acc[i][1]=0ull; }
  if (tid < KCL){ sSum[tid]=0.f; sSq[tid]=0.f; }

  for (int d0=0; d0<DIM; d0+=32){
    #pragma unroll
    for (int l=tid; l<2048; l+=256){
      int r=l>>5, c=l&31;
      As[r][c] = x[(row0+r)*DIM + d0 + c];
    }
    #pragma unroll
    for (int l=tid; l<2048; l+=256){
      int r=l>>6, c=l&63;
      Bs[r][c] = wc[(d0+r)*KCL + c];
    }
    __syncthreads();
    #pragma unroll
    for (int dd=0; dd<32; dd++){
      const ull* bp = reinterpret_cast<const ull*>(&Bs[dd][tx*4]);
      ull b0 = bp[0], b1 = bp[1];
      #pragma unroll
      for (int i=0;i<4;i++){
        float a = As[ty*4+i][dd];
        ull ap = pack2(a, a);
        ffma2(acc[i][0], ap, b0);
        ffma2(acc[i][1], ap, b1);
      }
    }
    __syncthreads();
  }
  float ps[4]={0,0,0,0}, pq[4]={0,0,0,0};
  #pragma unroll
  for (int i=0;i<4;i++){
    float v0=lo32(acc[i][0]), v1=hi32(acc[i][0]);
    float v2=lo32(acc[i][1]), v3=hi32(acc[i][1]);
    *reinterpret_cast<float4*>(&g_act[(row0+ty*4+i)*KCL + tx*4]) =
        make_float4(v0,v1,v2,v3);
    ps[0]+=v0; ps[1]+=v1; ps[2]+=v2; ps[3]+=v3;
    pq[0]+=v0*v0; pq[1]+=v1*v1; pq[2]+=v2*v2; pq[3]+=v3*v3;
  }
  #pragma unroll
  for (int j=0;j<4;j++){
    atomicAdd(&sSum[tx*4+j], ps[j]);
    atomicAdd(&sSq [tx*4+j], pq[j]);
  }
  __syncthreads();
  if (tid < KCL){
    atomicAdd(&g_colsum[tid],   sSum[tid]);
    atomicAdd(&g_colsumsq[tid], sSq[tid]);
  }
}

// ---------------- K2: BN1 + softmax (warp per row) + fused a_sum ------------
__global__ __launch_bounds__(256) void bn_softmax_kernel(
    const float* __restrict__ gamma, const float* __restrict__ beta){
  __shared__ float sbuf[8][KCL];
  int tid = threadIdx.x;
  int w = tid >> 5, lane = tid & 31;
  int row = blockIdx.x*8 + w;
  int b = row >> 9;
  const float inv_n = 1.f / (float)NROWS;
  int k2 = 2*lane;
  float2 cs = *reinterpret_cast<const float2*>(&g_colsum[k2]);
  float2 cq = *reinterpret_cast<const float2*>(&g_colsumsq[k2]);
  float2 ga = *reinterpret_cast<const float2*>(&gamma[k2]);
  float2 be = *reinterpret_cast<const float2*>(&beta[k2]);
  float m0 = cs.x*inv_n, m1 = cs.y*inv_n;
  float sc0 = ga.x*rsqrtf(cq.x*inv_n - m0*m0 + 1e-5f);
  float sc1 = ga.y*rsqrtf(cq.y*inv_n - m1*m1 + 1e-5f);
  float sh0 = be.x - m0*sc0, sh1 = be.y - m1*sc1;

  float2 v = *reinterpret_cast<const float2*>(&g_act[row*KCL + k2]);
  float vn0 = v.x*sc0 + sh0, vn1 = v.y*sc1 + sh1;
  float mx = fmaxf(vn0, vn1);
  #pragma unroll
  for (int o=16;o>0;o>>=1) mx = fmaxf(mx, __shfl_xor_sync(0xffffffffu, mx, o));
  float e0 = __expf(vn0 - mx), e1 = __expf(vn1 - mx);
  float s = e0 + e1;
  #pragma unroll
  for (int o=16;o>0;o>>=1) s += __shfl_xor_sync(0xffffffffu, s, o);
  float inv = 1.f / s;
  float p0 = e0*inv, p1 = e1*inv;
  *reinterpret_cast<float2*>(&g_act[row*KCL + k2]) = make_float2(p0, p1);
  *reinterpret_cast<float2*>(&sbuf[w][k2]) = make_float2(p0, p1);
  __syncthreads();
  if (tid < KCL){
    float t = 0.f;
    #pragma unroll
    for (int i=0;i<8;i++) t += sbuf[i][tid];
    atomicAdd(&g_asum[b*KCL + tid], t);
  }
}

// ---------------- K4: fv1[b,d,k]=sum_n a*x ; fv2=sum_n a*x*x ----------------
// grid (16 dtiles, 32 b), block 128. tile 64d x 64k, thread 8d x 4k.
__global__ __launch_bounds__(128) void einsum_kernel(const float* __restrict__ x){
  __shared__ float xs[16][64];
  __shared__ float as_[16][64];
  int tid = threadIdx.x;
  int b = blockIdx.y, dt0 = blockIdx.x*64;
  int kg = tid & 15, dg = tid >> 4;      // 16 x 8
  int k0 = kg*4, d0 = dg*8;
  ull f1[4][4], f2[4][4];                // [k][d-ull pair]
  #pragma unroll
  for (int kk=0;kk<4;kk++)
    #pragma unroll
    for (int j=0;j<4;j++){ f1[kk][j]=0ull; f2[kk][j]=0ull; }

  for (int n0=0; n0<NPTS; n0+=16){
    #pragma unroll
    for (int l=tid; l<256; l+=128){
      int r = l>>4, c = (l&15)*4;
      *reinterpret_cast<float4*>(&xs[r][c]) =
          *reinterpret_cast<const float4*>(&x[(b*NPTS + n0 + r)*DIM + dt0 + c]);
      *reinterpret_cast<float4*>(&as_[r][c]) =
          *reinterpret_cast<const float4*>(&g_act[(b*NPTS + n0 + r)*KCL + c]);
    }
    __syncthreads();
    #pragma unroll
    for (int nn=0; nn<16; nn++){
      const ull* xp = reinterpret_cast<const ull*>(&xs[nn][d0]);
      ull xv[4], qv[4];
      #pragma unroll
      for (int j=0;j<4;j++){ xv[j] = xp[j]; qv[j] = mul2(xv[j], xv[j]); }
      float4 av = *reinterpret_cast<const float4*>(&as_[nn][k0]);
      ull a0 = pack2(av.x, av.x), a1 = pack2(av.y, av.y);
      ull a2 = pack2(av.z, av.z), a3 = pack2(av.w, av.w);
      #pragma unroll
      for (int j=0;j<4;j++){
        ffma2(f1[0][j], xv[j], a0); ffma2(f1[1][j], xv[j], a1);
        ffma2(f1[2][j], xv[j], a2); ffma2(f1[3][j], xv[j], a3);
        ffma2(f2[0][j], qv[j], a0); ffma2(f2[1][j], qv[j], a1);
        ffma2(f2[2][j], qv[j], a2); ffma2(f2[3][j], qv[j], a3);
      }
    }
    __syncthreads();
  }
  #pragma unroll
  for (int j=0;j<4;j++){
    int d = dt0 + d0 + j*2;
    float4 v1a = make_float4(lo32(f1[0][j]),lo32(f1[1][j]),lo32(f1[2][j]),lo32(f1[3][j]));
    float4 v1b = make_float4(hi32(f1[0][j]),hi32(f1[1][j]),hi32(f1[2][j]),hi32(f1[3][j]));
    float4 v2a = make_float4(lo32(f2[0][j]),lo32(f2[1][j]),lo32(f2[2][j]),lo32(f2[3][j]));
    float4 v2b = make_float4(hi32(f2[0][j]),hi32(f2[1][j]),hi32(f2[2][j]),hi32(f2[3][j]));
    *reinterpret_cast<float4*>(&g_fv1[(b*DIM + d  )*KCL + k0]) = v1a;
    *reinterpret_cast<float4*>(&g_fv1[(b*DIM + d+1)*KCL + k0]) = v1b;
    *reinterpret_cast<float4*>(&g_fv2[(b*DIM + d  )*KCL + k0]) = v2a;
    *reinterpret_cast<float4*>(&g_fv2[(b*DIM + d+1)*KCL + k0]) = v2b;
  }
}

// ---------------- K5: FV transforms + per-(b,k) colnorm and per-b norm2 -----
__global__ __launch_bounds__(256) void fv_transform_kernel(
    const float* __restrict__ covw, const float* __restrict__ cw2w){
  int b = blockIdx.y, chunk = blockIdx.x;
  int tid = threadIdx.x;
  int k = tid & 63, dg = tid >> 6;
  float asum_k = g_asum[b*KCL + k];
  float pcol = 0.f, pn2 = 0.f;
  #pragma unroll 4
  for (int i=0;i<32;i++){
    int d = chunk*128 + i*4 + dg;
    int widx = d*KCL + k;
    int idx  = (b*DIM + d)*KCL + k;
    float cw2 = cw2w[widx];
    float cov = covw[widx];
    float cwv = cov*cov + 1e-6f;
    float rc = __fdividef(1.f, cwv);
    float f1r = g_fv1[idx], f2r = g_fv2[idx];
    float f1t = (f1r - asum_k*cw2) * rc;
    float f2t = (asum_k*cw2*cw2 + f2r - 2.f*f1r*cw2) * rc * rc - asum_k;
    g_fv1[idx] = f1t; g_fv2[idx] = f2t;
    pcol += f1t*f1t; pn2 += f2t*f2t;
  }
  __shared__ float sCol[KCL];
  __shared__ float sw[8];
  if (tid < KCL) sCol[tid] = 0.f;
  __syncthreads();
  atomicAdd(&sCol[k], pcol);
  #pragma unroll
  for (int o=16;o>0;o>>=1) pn2 += __shfl_xor_sync(0xffffffffu, pn2, o);
  if ((tid&31)==0) sw[tid>>5] = pn2;
  __syncthreads();
  if (tid < KCL) atomicAdd(&g_colnorm[b*KCL + tid], sCol[tid]);
  if (tid == 0){
    float t=0.f;
    #pragma unroll
    for (int i=0;i<8;i++) t += sw[i];
    atomicAdd(&g_norm2[b], t);
  }
}

// ---------------- K5b: tiny — fold the two-stage norms into scale tables ----
__global__ __launch_bounds__(64) void scale_kernel(){
  int b = blockIdx.x, k = threadIdx.x;
  float cn = g_colnorm[b*KCL + k];
  float inv1 = 1.f / fmaxf(sqrtf(cn), 1e-12f);
  float contrib = cn * inv1 * inv1;
  float t = contrib;
  #pragma unroll
  for (int o=16;o>0;o>>=1) t += __shfl_xor_sync(0xffffffffu, t, o);
  __shared__ float sw[2];
  if ((k&31)==0) sw[k>>5] = t;
  __syncthreads();
  float n1 = sqrtf(sw[0] + sw[1]);
  g_scale1[b*KCL + k] = inv1 / fmaxf(n1, 1e-12f);
  if (k == 0) g_scale2[b] = 1.f / fmaxf(sqrtf(g_norm2[b]), 1e-12f);
}

// ---------------- K6/K7a: out[32,1024] += A[32,chunk] @ W[chunk,1024] -------
// block 256 threads, o-tile 256; thread tile 4b x 8o (og=tid&31: cols
// q*128 + og*4, q in {0,1} -> exact disjoint cover of 256 cols).
// which=0: A = {g_fv1 | g_fv2} with fused norm scales -> g_fvout (hidden1)
// which=1: A = g_fvout -> g_gates
#define FC_KT 8
__global__ __launch_bounds__(256) void gemm_fc_kernel(
    const float* __restrict__ W, int ichunk, int which){
  __shared__ float Ws[FC_KT][256];
  __shared__ float fs[FC_KT][32];
  __shared__ float scl[BATCH*KCL];
  int tid = threadIdx.x;
  int o0 = blockIdx.x * 256;
  int i0 = blockIdx.y * ichunk;
  int og = tid & 31, bg = tid >> 5;  // 32 o-groups x 8 b-groups
  const float* A; float* out;
  int Alda, iA0; int half1 = 0;
  float sc2 = 1.f;
  int bload = tid & 31;              // batch row this thread loads
  int rload = tid >> 5;              // k-row this thread loads
  if (which == 0){
    out = g_fvout; Alda = HALF1;
    if (i0 < HALF1){ A = g_fv1; iA0 = i0; half1 = 1; }
    else { A = g_fv2; iA0 = i0 - HALF1; sc2 = g_scale2[bload]; }
    if (half1){
      for (int l = tid; l < BATCH*KCL; l += 256) scl[l] = g_scale1[l];
    }
  } else {
    A = g_fvout; out = g_gates; Alda = OUTF; iA0 = i0;
  }
  __syncthreads();

  ull acc[4][4];
  #pragma unroll
  for (int bb=0;bb<4;bb++)
    #pragma unroll
    for (int j=0;j<4;j++) acc[bb][j] = 0ull;

  for (int ic=0; ic<ichunk; ic+=FC_KT){
    int i = i0 + ic;
    int iA = iA0 + ic;
    // W tile: 8 x 256 floats, 2 float4 per thread
    #pragma unroll
    for (int p=0;p<2;p++){
      int off = p*1024 + tid*4;
      int r = off>>8, c = off&255;
      *reinterpret_cast<float4*>(&Ws[r][c]) =
          *reinterpret_cast<const float4*>(&W[(i+r)*OUTF + o0 + c]);
    }
    // A tile: 8 x 32, one element per thread, norm scales fused
    {
      float v = A[bload*Alda + iA + rload];
      if (which == 0){
        if (half1) v *= scl[bload*KCL + ((iA + rload) & 63)];
        else       v *= sc2;
      }
      fs[rload][bload] = v;
    }
    __syncthreads();
    #pragma unroll
    for (int ii=0; ii<FC_KT; ii++){
      float4 fv = *reinterpret_cast<const float4*>(&fs[ii][bg*4]);
      ull a0 = pack2(fv.x,fv.x), a1 = pack2(fv.y,fv.y);
      ull a2 = pack2(fv.z,fv.z), a3 = pack2(fv.w,fv.w);
      #pragma unroll
      for (int q=0;q<2;q++){
        const ull* wp = reinterpret_cast<const ull*>(&Ws[ii][q*128 + og*4]);
        ull w0 = wp[0], w1 = wp[1];
        ffma2(acc[0][q*2], a0, w0); ffma2(acc[0][q*2+1], a0, w1);
        ffma2(acc[1][q*2], a1, w0); ffma2(acc[1][q*2+1], a1, w1);
        ffma2(acc[2][q*2], a2, w0); ffma2(acc[2][q*2+1], a2, w1);
        ffma2(acc[3][q*2], a3, w0); ffma2(acc[3][q*2+1], a3, w1);
      }
    }
    __syncthreads();
  }
  #pragma unroll
  for (int bb=0;bb<4;bb++){
    int b = bg*4 + bb;
    #pragma unroll
    for (int q=0;q<2;q++)
      #pragma unroll
      for (int t=0;t<2;t++){
        int base = b*OUTF + o0 + q*128 + og*4 + t*2;
        atomicAdd(&out[base],   lo32(acc[bb][q*2+t]));
        atomicAdd(&out[base+1], hi32(acc[bb][q*2+t]));
      }
  }
}

// ---------------- K7b: BN2 (batch stats over 32) + sigmoid gate -------------
__global__ __launch_bounds__(256) void bn2_gate_kernel(
    const float* __restrict__ g2, const float* __restrict__ b2,
    float* __restrict__ out){
  int o = blockIdx.x*blockDim.x + threadIdx.x;   // 0..1023
  float m=0.f, s=0.f;
  #pragma unroll 8
  for (int b=0;b<BATCH;b++){ float v = g_gates[b*OUTF + o]; m += v; s += v*v; }
  m *= (1.f/BATCH);
  float var = s*(1.f/BATCH) - m*m;
  float rs = rsqrtf(var + 1e-5f);
  float ga = g2[o], be = b2[o];
  #pragma unroll 8
  for (int b=0;b<BATCH;b++){
    float v = (g_gates[b*OUTF + o] - m)*rs*ga + be;
    float sig = 1.f/(1.f + expf(-v));
    out[b*OUTF + o] = g_fvout[b*OUTF + o] * sig;
  }
}

// ---------------------------------------------------------------------------
extern "C" void kernel_launch(void* const* d_in, const int* in_sizes, int n_in,
                              void* d_out, int out_size){
  const float* x   = (const float*)d_in[0];   // [32,512,1024]
  const float* wc  = (const float*)d_in[1];   // [1024,64]
  const float* cov = (const float*)d_in[2];   // [1024,64]
  const float* cw2 = (const float*)d_in[3];   // [1,1024,64]
  const float* w1  = (const float*)d_in[4];   // [131072,1024]
  const float* g1  = (const float*)d_in[5];   // [64]
  const float* b1  = (const float*)d_in[6];   // [64]
  const float* wg  = (const float*)d_in[7];   // [1024,1024]
  const float* g2  = (const float*)d_in[8];   // [1024]
  const float* b2  = (const float*)d_in[9];   // [1024]
  float* out = (float*)d_out;                 // [32,1024]

  zero_kernel<<<128, 256>>>();
  gemm_act_kernel<<<256, 256>>>(x, wc);
  bn_softmax_kernel<<<2048, 256>>>(g1, b1);
  einsum_kernel<<<dim3(16, 32), 128>>>(x);
  fv_transform_kernel<<<dim3(8, 32), 256>>>(cov, cw2);
  scale_kernel<<<BATCH, 64>>>();
  gemm_fc_kernel<<<dim3(4, 64), 256>>>(w1, 2048, 0);  // hidden1
  gemm_fc_kernel<<<dim3(4, 8),  256>>>(wg, 128, 1);   // gating
  bn2_gate_kernel<<<4, 256>>>(g2, b2, out);
}

// round 7
// speedup vs baseline: 1.1027x; 1.1027x over previous
#include <cuda_runtime.h>

#define BATCH 32
#define NPTS 512
#define DIM 1024
#define KCL 64
#define NROWS (BATCH*NPTS)      /* 16384 */
#define OUTF 1024
#define IN2 (2*DIM*KCL)         /* 131072 */
#define HALF1 (DIM*KCL)         /* 65536 */

// ---------------- scratch (device globals: no allocations allowed) ----------
__device__ float g_act[NROWS*KCL];          // 4 MB
__device__ float g_colsum[KCL];
__device__ float g_colsumsq[KCL];
__device__ float g_asum[BATCH*KCL];
__device__ float g_fv1[BATCH*DIM*KCL];      // 8 MB
__device__ float g_fv2[BATCH*DIM*KCL];      // 8 MB
__device__ float g_colnorm[BATCH*KCL];
__device__ float g_norm2[BATCH];
__device__ float g_scale1[BATCH*KCL];
__device__ float g_scale2[BATCH];
__device__ float g_fvout[BATCH*OUTF];
__device__ float g_gates[BATCH*OUTF];

typedef unsigned long long ull;

// ---------------- f32x2 helpers (FFMA2: 2 FMAs / instr on sm_103a) ----------
__device__ __forceinline__ ull pack2(float lo, float hi){
  ull r;
  asm("mov.b64 %0, {%1, %2};" : "=l"(r)
      : "r"(__float_as_uint(lo)), "r"(__float_as_uint(hi)));
  return r;
}
__device__ __forceinline__ void ffma2(ull &d, ull a, ull b){
  asm("fma.rn.f32x2 %0, %1, %2, %3;" : "=l"(d) : "l"(a), "l"(b), "l"(d));
}
__device__ __forceinline__ ull mul2(ull a, ull b){
  ull r; asm("mul.rn.f32x2 %0, %1, %2;" : "=l"(r) : "l"(a), "l"(b)); return r;
}
__device__ __forceinline__ float lo32(ull v){ return __uint_as_float((unsigned)(v & 0xffffffffull)); }
__device__ __forceinline__ float hi32(ull v){ return __uint_as_float((unsigned)(v >> 32)); }

// ---------------- K0: zero the atomic accumulators ---------------------------
__global__ void zero_kernel(){
  int i = blockIdx.x*blockDim.x + threadIdx.x;
  if (i < BATCH*OUTF){ g_fvout[i] = 0.f; g_gates[i] = 0.f; }
  if (i < BATCH*KCL){ g_colnorm[i] = 0.f; g_asum[i] = 0.f; }
  if (i < KCL){ g_colsum[i] = 0.f; g_colsumsq[i] = 0.f; }
  if (i < BATCH) g_norm2[i] = 0.f;
}

// ---------------- K1: act_raw = X @ Wc  (+ column sum / sumsq for BN1) ------
__global__ __launch_bounds__(256) void gemm_act_kernel(
    const float* __restrict__ x, const float* __restrict__ wc){
  __shared__ float As[64][33];
  __shared__ float Bs[32][64];
  __shared__ float sSum[KCL], sSq[KCL];
  int tid = threadIdx.x;
  int row0 = blockIdx.x * 64;
  int tx = tid & 15, ty = tid >> 4;
  ull acc[4][2];
  #pragma unroll
  for (int i=0;i<4;i++){ acc[i][0]=0ull; acc[i][1]=0ull; }
  if (tid < KCL){ sSum[tid]=0.f; sSq[tid]=0.f; }

  for (int d0=0; d0<DIM; d0+=32){
    #pragma unroll
    for (int l=tid; l<2048; l+=256){
      int r=l>>5, c=l&31;
      As[r][c] = x[(row0+r)*DIM + d0 + c];
    }
    #pragma unroll
    for (int l=tid; l<2048; l+=256){
      int r=l>>6, c=l&63;
      Bs[r][c] = wc[(d0+r)*KCL + c];
    }
    __syncthreads();
    #pragma unroll
    for (int dd=0; dd<32; dd++){
      const ull* bp = reinterpret_cast<const ull*>(&Bs[dd][tx*4]);
      ull b0 = bp[0], b1 = bp[1];
      #pragma unroll
      for (int i=0;i<4;i++){
        float a = As[ty*4+i][dd];
        ull ap = pack2(a, a);
        ffma2(acc[i][0], ap, b0);
        ffma2(acc[i][1], ap, b1);
      }
    }
    __syncthreads();
  }
  float ps[4]={0,0,0,0}, pq[4]={0,0,0,0};
  #pragma unroll
  for (int i=0;i<4;i++){
    float v0=lo32(acc[i][0]), v1=hi32(acc[i][0]);
    float v2=lo32(acc[i][1]), v3=hi32(acc[i][1]);
    *reinterpret_cast<float4*>(&g_act[(row0+ty*4+i)*KCL + tx*4]) =
        make_float4(v0,v1,v2,v3);
    ps[0]+=v0; ps[1]+=v1; ps[2]+=v2; ps[3]+=v3;
    pq[0]+=v0*v0; pq[1]+=v1*v1; pq[2]+=v2*v2; pq[3]+=v3*v3;
  }
  #pragma unroll
  for (int j=0;j<4;j++){
    atomicAdd(&sSum[tx*4+j], ps[j]);
    atomicAdd(&sSq [tx*4+j], pq[j]);
  }
  __syncthreads();
  if (tid < KCL){
    atomicAdd(&g_colsum[tid],   sSum[tid]);
    atomicAdd(&g_colsumsq[tid], sSq[tid]);
  }
}

// ---------------- K2: BN1 + softmax (warp per row) + fused a_sum ------------
__global__ __launch_bounds__(256) void bn_softmax_kernel(
    const float* __restrict__ gamma, const float* __restrict__ beta){
  __shared__ float sbuf[8][KCL];
  int tid = threadIdx.x;
  int w = tid >> 5, lane = tid & 31;
  int row = blockIdx.x*8 + w;
  int b = row >> 9;
  const float inv_n = 1.f / (float)NROWS;
  int k2 = 2*lane;
  float2 cs = *reinterpret_cast<const float2*>(&g_colsum[k2]);
  float2 cq = *reinterpret_cast<const float2*>(&g_colsumsq[k2]);
  float2 ga = *reinterpret_cast<const float2*>(&gamma[k2]);
  float2 be = *reinterpret_cast<const float2*>(&beta[k2]);
  float m0 = cs.x*inv_n, m1 = cs.y*inv_n;
  float sc0 = ga.x*rsqrtf(cq.x*inv_n - m0*m0 + 1e-5f);
  float sc1 = ga.y*rsqrtf(cq.y*inv_n - m1*m1 + 1e-5f);
  float sh0 = be.x - m0*sc0, sh1 = be.y - m1*sc1;

  float2 v = *reinterpret_cast<const float2*>(&g_act[row*KCL + k2]);
  float vn0 = v.x*sc0 + sh0, vn1 = v.y*sc1 + sh1;
  float mx = fmaxf(vn0, vn1);
  #pragma unroll
  for (int o=16;o>0;o>>=1) mx = fmaxf(mx, __shfl_xor_sync(0xffffffffu, mx, o));
  float e0 = __expf(vn0 - mx), e1 = __expf(vn1 - mx);
  float s = e0 + e1;
  #pragma unroll
  for (int o=16;o>0;o>>=1) s += __shfl_xor_sync(0xffffffffu, s, o);
  float inv = 1.f / s;
  float p0 = e0*inv, p1 = e1*inv;
  *reinterpret_cast<float2*>(&g_act[row*KCL + k2]) = make_float2(p0, p1);
  *reinterpret_cast<float2*>(&sbuf[w][k2]) = make_float2(p0, p1);
  __syncthreads();
  if (tid < KCL){
    float t = 0.f;
    #pragma unroll
    for (int i=0;i<8;i++) t += sbuf[i][tid];
    atomicAdd(&g_asum[b*KCL + tid], t);
  }
}

// ---------------- K4: einsum + fused covariance transform + norm partials ---
// grid (16 dtiles, 32 b), block 128. tile 64d x 64k, thread 8d x 4k, NT=32.
__global__ __launch_bounds__(128) void einsum_kernel(
    const float* __restrict__ x,
    const float* __restrict__ covw, const float* __restrict__ cw2w){
  __shared__ float xs[32][64];
  __shared__ float as_[32][64];
  __shared__ float sCol[KCL];
  __shared__ float swp[4];
  int tid = threadIdx.x;
  int b = blockIdx.y, dt0 = blockIdx.x*64;
  int kg = tid & 15, dg = tid >> 4;      // 16 x 8
  int k0 = kg*4, d0 = dg*8;
  ull f1[4][4], f2[4][4];                // [k][d-ull pair]
  #pragma unroll
  for (int kk=0;kk<4;kk++)
    #pragma unroll
    for (int j=0;j<4;j++){ f1[kk][j]=0ull; f2[kk][j]=0ull; }

  for (int n0=0; n0<NPTS; n0+=32){
    #pragma unroll
    for (int l=tid; l<512; l+=128){
      int r = l>>4, c = (l&15)*4;
      *reinterpret_cast<float4*>(&xs[r][c]) =
          *reinterpret_cast<const float4*>(&x[(b*NPTS + n0 + r)*DIM + dt0 + c]);
      *reinterpret_cast<float4*>(&as_[r][c]) =
          *reinterpret_cast<const float4*>(&g_act[(b*NPTS + n0 + r)*KCL + c]);
    }
    __syncthreads();
    #pragma unroll
    for (int nn=0; nn<32; nn++){
      const ull* xp = reinterpret_cast<const ull*>(&xs[nn][d0]);
      ull xv[4], qv[4];
      #pragma unroll
      for (int j=0;j<4;j++){ xv[j] = xp[j]; qv[j] = mul2(xv[j], xv[j]); }
      float4 av = *reinterpret_cast<const float4*>(&as_[nn][k0]);
      ull a0 = pack2(av.x, av.x), a1 = pack2(av.y, av.y);
      ull a2 = pack2(av.z, av.z), a3 = pack2(av.w, av.w);
      #pragma unroll
      for (int j=0;j<4;j++){
        ffma2(f1[0][j], xv[j], a0); ffma2(f1[1][j], xv[j], a1);
        ffma2(f1[2][j], xv[j], a2); ffma2(f1[3][j], xv[j], a3);
        ffma2(f2[0][j], qv[j], a0); ffma2(f2[1][j], qv[j], a1);
        ffma2(f2[2][j], qv[j], a2); ffma2(f2[3][j], qv[j], a3);
      }
    }
    __syncthreads();
  }

  // ---- fused transform epilogue (was fv_transform_kernel) ----
  float4 asv = *reinterpret_cast<const float4*>(&g_asum[b*KCL + k0]);
  float asm_[4] = {asv.x, asv.y, asv.z, asv.w};
  float pcol[4] = {0.f,0.f,0.f,0.f};
  float pn2 = 0.f;
  #pragma unroll
  for (int j=0;j<4;j++){
    int dbase = dt0 + d0 + j*2;
    #pragma unroll
    for (int h=0; h<2; h++){
      int dd = dbase + h;
      float4 cw = *reinterpret_cast<const float4*>(&cw2w[dd*KCL + k0]);
      float4 cv = *reinterpret_cast<const float4*>(&covw[dd*KCL + k0]);
      float f1v[4], f2v[4];
      #pragma unroll
      for (int m=0;m<4;m++){
        f1v[m] = h ? hi32(f1[m][j]) : lo32(f1[m][j]);
        f2v[m] = h ? hi32(f2[m][j]) : lo32(f2[m][j]);
      }
      float o1[4], o2[4];
      const float* cwp = &cw.x;
      const float* cvp = &cv.x;
      #pragma unroll
      for (int m=0;m<4;m++){
        float cwm = cwp[m], cvm = cvp[m];
        float cwv = cvm*cvm + 1e-6f;
        float rc = __fdividef(1.f, cwv);
        float f1t = (f1v[m] - asm_[m]*cwm) * rc;
        float f2t = (asm_[m]*cwm*cwm + f2v[m] - 2.f*f1v[m]*cwm) * rc * rc - asm_[m];
        o1[m] = f1t; o2[m] = f2t;
        pcol[m] += f1t*f1t; pn2 += f2t*f2t;
      }
      *reinterpret_cast<float4*>(&g_fv1[(b*DIM + dd)*KCL + k0]) =
          make_float4(o1[0],o1[1],o1[2],o1[3]);
      *reinterpret_cast<float4*>(&g_fv2[(b*DIM + dd)*KCL + k0]) =
          make_float4(o2[0],o2[1],o2[2],o2[3]);
    }
  }
  // block reductions
  if (tid < KCL) sCol[tid] = 0.f;
  __syncthreads();
  #pragma unroll
  for (int m=0;m<4;m++) atomicAdd(&sCol[k0+m], pcol[m]);
  #pragma unroll
  for (int o=16;o>0;o>>=1) pn2 += __shfl_xor_sync(0xffffffffu, pn2, o);
  if ((tid&31)==0) swp[tid>>5] = pn2;
  __syncthreads();
  if (tid < KCL) atomicAdd(&g_colnorm[b*KCL + tid], sCol[tid]);
  if (tid == 0)
    atomicAdd(&g_norm2[b], swp[0]+swp[1]+swp[2]+swp[3]);
}

// ---------------- K5b: tiny — fold the two-stage norms into scale tables ----
__global__ __launch_bounds__(64) void scale_kernel(){
  int b = blockIdx.x, k = threadIdx.x;
  float cn = g_colnorm[b*KCL + k];
  float inv1 = 1.f / fmaxf(sqrtf(cn), 1e-12f);
  float contrib = cn * inv1 * inv1;
  float t = contrib;
  #pragma unroll
  for (int o=16;o>0;o>>=1) t += __shfl_xor_sync(0xffffffffu, t, o);
  __shared__ float sw[2];
  if ((k&31)==0) sw[k>>5] = t;
  __syncthreads();
  float n1 = sqrtf(sw[0] + sw[1]);
  g_scale1[b*KCL + k] = inv1 / fmaxf(n1, 1e-12f);
  if (k == 0) g_scale2[b] = 1.f / fmaxf(sqrtf(g_norm2[b]), 1e-12f);
}

// ---------------- K6/K7a: out[32,1024] += A[32,chunk] @ W[chunk,1024] -------
// Double-buffered smem + register prefetch: one sync per k-tile, DRAM latency
// overlapped with 256 fma-cycles of compute.
// block 256 threads, o-tile 256; thread tile 4b x 8o (cols q*128+og*4, q in
// {0,1} -> exact disjoint cover of 256 cols).
#define FC_KT 8
__global__ __launch_bounds__(256) void gemm_fc_kernel(
    const float* __restrict__ W, int ichunk, int which){
  __shared__ float Ws[2][FC_KT][256];
  __shared__ float fs[2][FC_KT][32];
  __shared__ float scl[BATCH*KCL];
  int tid = threadIdx.x;
  int o0 = blockIdx.x * 256;
  int i0 = blockIdx.y * ichunk;
  int og = tid & 31, bg = tid >> 5;  // 32 o-groups x 8 b-groups
  const float* A; float* out;
  int Alda, iA0; int half1 = 0;
  float sc2 = 1.f;
  int bload = tid & 31;              // batch row this thread loads
  int rload = tid >> 5;              // k-row this thread loads
  if (which == 0){
    out = g_fvout; Alda = HALF1;
    if (i0 < HALF1){ A = g_fv1; iA0 = i0; half1 = 1; }
    else { A = g_fv2; iA0 = i0 - HALF1; sc2 = g_scale2[bload]; }
    if (half1){
      for (int l = tid; l < BATCH*KCL; l += 256) scl[l] = g_scale1[l];
    }
  } else {
    A = g_fvout; out = g_gates; Alda = OUTF; iA0 = i0;
  }
  __syncthreads();

  int T = ichunk / FC_KT;
  // W tile load offsets for this thread
  int off0 = tid*4;
  int r0 = off0 >> 8,  c0 = off0 & 255;
  int off1 = 1024 + tid*4;
  int r1 = off1 >> 8,  c1 = off1 & 255;

  ull acc[4][4];
  #pragma unroll
  for (int bb=0;bb<4;bb++)
    #pragma unroll
    for (int j=0;j<4;j++) acc[bb][j] = 0ull;

  // prefetch tile 0
  float4 pw0, pw1; float pa;
  {
    int i = i0;
    pw0 = *reinterpret_cast<const float4*>(&W[(i+r0)*OUTF + o0 + c0]);
    pw1 = *reinterpret_cast<const float4*>(&W[(i+r1)*OUTF + o0 + c1]);
    float v = A[bload*Alda + iA0 + rload];
    if (which == 0){
      if (half1) v *= scl[bload*KCL + ((iA0 + rload) & 63)];
      else       v *= sc2;
    }
    pa = v;
  }
  *reinterpret_cast<float4*>(&Ws[0][r0][c0]) = pw0;
  *reinterpret_cast<float4*>(&Ws[0][r1][c1]) = pw1;
  fs[0][rload][bload] = pa;
  __syncthreads();

  for (int t=0; t<T; t++){
    int cur = t & 1;
    bool more = (t+1) < T;
    if (more){
      int i  = i0  + (t+1)*FC_KT;
      int iA = iA0 + (t+1)*FC_KT;
      pw0 = *reinterpret_cast<const float4*>(&W[(i+r0)*OUTF + o0 + c0]);
      pw1 = *reinterpret_cast<const float4*>(&W[(i+r1)*OUTF + o0 + c1]);
      float v = A[bload*Alda + iA + rload];
      if (which == 0){
        if (half1) v *= scl[bload*KCL + ((iA + rload) & 63)];
        else       v *= sc2;
      }
      pa = v;
    }
    #pragma unroll
    for (int ii=0; ii<FC_KT; ii++){
      float4 fv = *reinterpret_cast<const float4*>(&fs[cur][ii][bg*4]);
      ull a0 = pack2(fv.x,fv.x), a1 = pack2(fv.y,fv.y);
      ull a2 = pack2(fv.z,fv.z), a3 = pack2(fv.w,fv.w);
      #pragma unroll
      for (int q=0;q<2;q++){
        const ull* wp = reinterpret_cast<const ull*>(&Ws[cur][ii][q*128 + og*4]);
        ull w0 = wp[0], w1 = wp[1];
        ffma2(acc[0][q*2], a0, w0); ffma2(acc[0][q*2+1], a0, w1);
        ffma2(acc[1][q*2], a1, w0); ffma2(acc[1][q*2+1], a1, w1);
        ffma2(acc[2][q*2], a2, w0); ffma2(acc[2][q*2+1], a2, w1);
        ffma2(acc[3][q*2], a3, w0); ffma2(acc[3][q*2+1], a3, w1);
      }
    }
    if (more){
      int nxt = (t+1) & 1;
      *reinterpret_cast<float4*>(&Ws[nxt][r0][c0]) = pw0;
      *reinterpret_cast<float4*>(&Ws[nxt][r1][c1]) = pw1;
      fs[nxt][rload][bload] = pa;
    }
    __syncthreads();
  }

  #pragma unroll
  for (int bb=0;bb<4;bb++){
    int b = bg*4 + bb;
    #pragma unroll
    for (int q=0;q<2;q++)
      #pragma unroll
      for (int t=0;t<2;t++){
        int base = b*OUTF + o0 + q*128 + og*4 + t*2;
        atomicAdd(&out[base],   lo32(acc[bb][q*2+t]));
        atomicAdd(&out[base+1], hi32(acc[bb][q*2+t]));
      }
  }
}

// ---------------- K7b: BN2 (batch stats over 32) + sigmoid gate -------------
__global__ __launch_bounds__(256) void bn2_gate_kernel(
    const float* __restrict__ g2, const float* __restrict__ b2,
    float* __restrict__ out){
  int o = blockIdx.x*blockDim.x + threadIdx.x;   // 0..1023
  float m=0.f, s=0.f;
  #pragma unroll 8
  for (int b=0;b<BATCH;b++){ float v = g_gates[b*OUTF + o]; m += v; s += v*v; }
  m *= (1.f/BATCH);
  float var = s*(1.f/BATCH) - m*m;
  float rs = rsqrtf(var + 1e-5f);
  float ga = g2[o], be = b2[o];
  #pragma unroll 8
  for (int b=0;b<BATCH;b++){
    float v = (g_gates[b*OUTF + o] - m)*rs*ga + be;
    float sig = 1.f/(1.f + expf(-v));
    out[b*OUTF + o] = g_fvout[b*OUTF + o] * sig;
  }
}

// ---------------------------------------------------------------------------
extern "C" void kernel_launch(void* const* d_in, const int* in_sizes, int n_in,
                              void* d_out, int out_size){
  const float* x   = (const float*)d_in[0];   // [32,512,1024]
  const float* wc  = (const float*)d_in[1];   // [1024,64]
  const float* cov = (const float*)d_in[2];   // [1024,64]
  const float* cw2 = (const float*)d_in[3];   // [1,1024,64]
  const float* w1  = (const float*)d_in[4];   // [131072,1024]
  const float* g1  = (const float*)d_in[5];   // [64]
  const float* b1  = (const float*)d_in[6];   // [64]
  const float* wg  = (const float*)d_in[7];   // [1024,1024]
  const float* g2  = (const float*)d_in[8];   // [1024]
  const float* b2  = (const float*)d_in[9];   // [1024]
  float* out = (float*)d_out;                 // [32,1024]

  zero_kernel<<<128, 256>>>();
  gemm_act_kernel<<<256, 256>>>(x, wc);
  bn_softmax_kernel<<<2048, 256>>>(g1, b1);
  einsum_kernel<<<dim3(16, 32), 128>>>(x, cov, cw2);
  scale_kernel<<<BATCH, 64>>>();
  gemm_fc_kernel<<<dim3(4, 64), 256>>>(w1, 2048, 0);  // hidden1
  gemm_fc_kernel<<<dim3(4, 8),  256>>>(wg, 128, 1);   // gating
  bn2_gate_kernel<<<4, 256>>>(g2, b2, out);
}